// round 1
// baseline (speedup 1.0000x reference)
#include <cuda_runtime.h>

// ---------------- problem constants ----------------
#define B_   2048
#define T_   168
#define H_   128
#define G_   512     // 4*H
#define K2_  256     // concat input dim (128 input + 128 hidden)
#define BM_  16      // batch rows per CTA
#define FN_  32
#define HOR_ 24

// ---------------- device scratch (no allocs allowed) ----------------
__device__ float g_wpack[2 * K2_ * G_];          // [l][k][g]  k-major packed weights (1 MB)
__device__ float g_bsum [2 * G_];                // b_ih + b_hh
__device__ float g_hs   [(size_t)B_ * T_ * H_];  // last-layer hidden at every step (176 MB)

// ---------------- fast activations (fp32, safe range) ----------------
__device__ __forceinline__ float sigf(float x) {
    return __fdividef(1.f, 1.f + __expf(-x));
}
__device__ __forceinline__ float tanhfast(float x) {
    x = fminf(fmaxf(x, -30.f), 30.f);
    float e = __expf(-2.f * x);
    return __fdividef(1.f - e, 1.f + e);
}

// ---------------- weight packing: Wpack[l][k][g] ----------------
// k <  128 : W_ih[l][g][k]
// k >= 128 : W_hh[l][g][k-128]
__global__ void pack_kernel(const float* __restrict__ W_ih, const float* __restrict__ W_hh,
                            const float* __restrict__ b_ih, const float* __restrict__ b_hh) {
    int idx = blockIdx.x * blockDim.x + threadIdx.x;     // 0 .. 262143
    int l = idx >> 17;
    int k = (idx >> 9) & 255;
    int g = idx & 511;
    float v = (k < 128) ? W_ih[l * 65536 + g * 128 + k]
                        : W_hh[l * 65536 + g * 128 + (k - 128)];
    g_wpack[idx] = v;
    if (idx < 2 * G_) g_bsum[idx] = b_ih[idx] + b_hh[idx];
}

// ---------------- per-CTA GEMM: G[16][512] = A[16][256] * Wpack + bsum ----------------
// thread: cg = tid&127 -> 4 gate cols [4cg..4cg+3]; rg = tid>>7 -> rows [8rg..8rg+7]
__device__ __forceinline__ void gemm16(const float4* __restrict__ A4,     // [16][64] float4
                                       const float*  __restrict__ W,      // [256][512]
                                       const float*  __restrict__ bsum,   // [512]
                                       float4* __restrict__ G4,           // [16][128] float4
                                       int cg, int r0) {
    const float4* W4 = (const float4*)W;     // [256][128]
    float4 bs = ((const float4*)bsum)[cg];
    float4 acc[8];
#pragma unroll
    for (int r = 0; r < 8; r++) acc[r] = bs;

    // software prefetch of the 4 weight rows (k = 4*k4 .. 4*k4+3)
    float4 wn0 = W4[0 * 128 + cg];
    float4 wn1 = W4[1 * 128 + cg];
    float4 wn2 = W4[2 * 128 + cg];
    float4 wn3 = W4[3 * 128 + cg];

    for (int k4 = 0; k4 < 64; k4++) {
        float4 w0 = wn0, w1 = wn1, w2 = wn2, w3 = wn3;
        int kn = (k4 < 63) ? (k4 + 1) * 4 : 252;   // redundant reload on last iter (no OOB)
        wn0 = W4[(kn + 0) * 128 + cg];
        wn1 = W4[(kn + 1) * 128 + cg];
        wn2 = W4[(kn + 2) * 128 + cg];
        wn3 = W4[(kn + 3) * 128 + cg];
#pragma unroll
        for (int r = 0; r < 8; r++) {
            float4 a = A4[(r0 + r) * 64 + k4];    // broadcast LDS within warp
            acc[r].x = fmaf(a.x, w0.x, acc[r].x);
            acc[r].y = fmaf(a.x, w0.y, acc[r].y);
            acc[r].z = fmaf(a.x, w0.z, acc[r].z);
            acc[r].w = fmaf(a.x, w0.w, acc[r].w);
            acc[r].x = fmaf(a.y, w1.x, acc[r].x);
            acc[r].y = fmaf(a.y, w1.y, acc[r].y);
            acc[r].z = fmaf(a.y, w1.z, acc[r].z);
            acc[r].w = fmaf(a.y, w1.w, acc[r].w);
            acc[r].x = fmaf(a.z, w2.x, acc[r].x);
            acc[r].y = fmaf(a.z, w2.y, acc[r].y);
            acc[r].z = fmaf(a.z, w2.z, acc[r].z);
            acc[r].w = fmaf(a.z, w2.w, acc[r].w);
            acc[r].x = fmaf(a.w, w3.x, acc[r].x);
            acc[r].y = fmaf(a.w, w3.y, acc[r].y);
            acc[r].z = fmaf(a.w, w3.z, acc[r].z);
            acc[r].w = fmaf(a.w, w3.w, acc[r].w);
        }
    }
#pragma unroll
    for (int r = 0; r < 8; r++) G4[(r0 + r) * 128 + cg] = acc[r];
}

// ---------------- persistent recurrent kernel: 128 CTAs x 16 rows ----------------
// dyn smem layout (floats):
//  As[16][256]  (xc | h0)      4096
//  Bs[16][256]  (h0new | h1)   4096
//  C0[16][128]                 2048
//  C1[16][128]                 2048
//  Gs[16][512]                 8192
//  Xs[16][168]                 2688
#define LSTM_SMEM_FLOATS (4096 + 4096 + 2048 + 2048 + 8192 + 2688)

__global__ __launch_bounds__(256, 1) void lstm_kernel(const float* __restrict__ x,
                                                      const float* __restrict__ hw,
                                                      const float* __restrict__ hb) {
    extern __shared__ float sm[];
    float* As = sm;
    float* Bs = As + 4096;
    float* C0 = Bs + 4096;
    float* C1 = C0 + 2048;
    float* Gs = C1 + 2048;
    float* Xs = Gs + 8192;

    int tid = threadIdx.x;
    int b0  = blockIdx.x * BM_;
    int cg  = tid & 127;
    int rg  = tid >> 7;
    int r0  = rg * 8;

    // init hidden/cell state + stage x tile
    for (int i = tid; i < BM_ * H_; i += 256) {
        int r = i >> 7, j = i & 127;
        As[r * 256 + 128 + j] = 0.f;
        Bs[r * 256 + 128 + j] = 0.f;
        C0[i] = 0.f;
        C1[i] = 0.f;
    }
    for (int i = tid; i < BM_ * T_; i += 256) {
        int r = i / T_, t = i - r * T_;
        Xs[r * T_ + t] = x[(size_t)(b0 + r) * T_ + t];
    }
    float hwv = hw[cg];
    float hbv = hb[cg];
    __syncthreads();

    const float4* A4 = (const float4*)As;
    const float4* B4 = (const float4*)Bs;
    float4* G4 = (float4*)Gs;

    for (int t = 0; t < T_; t++) {
        // xc = relu(x*hw + hb) into As[:,0:128]
#pragma unroll
        for (int i = 0; i < 8; i++) {
            int r = rg + 2 * i;
            As[r * 256 + cg] = fmaxf(Xs[r * T_ + t] * hwv + hbv, 0.f);
        }
        __syncthreads();

        // layer 0 gates
        gemm16(A4, g_wpack, g_bsum, G4, cg, r0);
        __syncthreads();

        // cell 0
#pragma unroll
        for (int i = 0; i < 8; i++) {
            int r = rg + 2 * i;
            float ig = Gs[r * 512 + cg];
            float fg = Gs[r * 512 + 128 + cg];
            float gg = Gs[r * 512 + 256 + cg];
            float og = Gs[r * 512 + 384 + cg];
            float c  = sigf(fg) * C0[r * 128 + cg] + sigf(ig) * tanhfast(gg);
            float h  = sigf(og) * tanhfast(c);
            C0[r * 128 + cg]      = c;
            Bs[r * 256 + cg]      = h;   // layer-1 input
            As[r * 256 + 128 + cg] = h;  // next-step layer-0 recurrent input
        }
        __syncthreads();

        // layer 1 gates
        gemm16(B4, g_wpack + 131072, g_bsum + 512, G4, cg, r0);
        __syncthreads();

        // cell 1 (+ store hidden history)
#pragma unroll
        for (int i = 0; i < 8; i++) {
            int r = rg + 2 * i;
            float ig = Gs[r * 512 + cg];
            float fg = Gs[r * 512 + 128 + cg];
            float gg = Gs[r * 512 + 256 + cg];
            float og = Gs[r * 512 + 384 + cg];
            float c  = sigf(fg) * C1[r * 128 + cg] + sigf(ig) * tanhfast(gg);
            float h  = sigf(og) * tanhfast(c);
            C1[r * 128 + cg]       = c;
            Bs[r * 256 + 128 + cg] = h;
            g_hs[((size_t)(b0 + r) * T_ + t) * H_ + cg] = h;
        }
        // no trailing sync needed: next write (xc -> As[:,0:128]) is disjoint,
        // and the after-xc sync orders cell1 before the next gemm.
    }
}

// ---------------- attention + head: one CTA per batch element ----------------
__global__ __launch_bounds__(128) void attn_kernel(
    const float* __restrict__ conv_W, const float* __restrict__ conv_b,
    const float* __restrict__ lin1_W, const float* __restrict__ lin1_b,
    const float* __restrict__ lin2_W, const float* __restrict__ lin2_b,
    const float* __restrict__ out_W,  const float* __restrict__ out_b,
    float* __restrict__ out) {
    __shared__ float cw[FN_ * T_];     // [32][168], t=167 zero-padded
    __shared__ float convs[FN_ * H_];  // conv[b] flat f*128+k (pre-relu)
    __shared__ float htt[H_];
    __shared__ float wv[FN_];
    __shared__ float alpha[H_];
    __shared__ float vv[FN_];
    __shared__ float nh[H_];

    int tid = threadIdx.x;
    int b   = blockIdx.x;

    for (int i = tid; i < FN_ * T_; i += 128) {
        int f = i / T_, t = i - f * T_;
        cw[i] = (t < T_ - 1) ? conv_W[f * (T_ - 1) + t] : 0.f;
    }
    __syncthreads();

    // conv[b,f,k] = sum_t relu(hs[b,t,k]) * conv_W[f,t]   (thread owns k = tid)
    int k = tid;
    float acc[FN_];
#pragma unroll
    for (int f = 0; f < FN_; f++) acc[f] = 0.f;
    const float* hsb = g_hs + (size_t)b * T_ * H_;
    const float4* cw4 = (const float4*)cw;   // [32][42]
    for (int t4 = 0; t4 < 42; t4++) {
        float h0v = fmaxf(hsb[(t4 * 4 + 0) * H_ + k], 0.f);
        float h1v = fmaxf(hsb[(t4 * 4 + 1) * H_ + k], 0.f);
        float h2v = fmaxf(hsb[(t4 * 4 + 2) * H_ + k], 0.f);
        float h3v = fmaxf(hsb[(t4 * 4 + 3) * H_ + k], 0.f);
#pragma unroll
        for (int f = 0; f < FN_; f++) {
            float4 c4 = cw4[f * 42 + t4];
            acc[f] = fmaf(h0v, c4.x, acc[f]);
            acc[f] = fmaf(h1v, c4.y, acc[f]);
            acc[f] = fmaf(h2v, c4.z, acc[f]);
            acc[f] = fmaf(h3v, c4.w, acc[f]);
        }
    }
#pragma unroll
    for (int f = 0; f < FN_; f++) convs[f * H_ + k] = acc[f] + conv_b[f];
    htt[k] = hsb[(T_ - 1) * H_ + k];
    __syncthreads();

    // w = htt @ lin1_W.T + lin1_b
    if (tid < FN_) {
        float s = lin1_b[tid];
        for (int kk = 0; kk < H_; kk++) s = fmaf(htt[kk], lin1_W[tid * H_ + kk], s);
        wv[tid] = s;
    }
    __syncthreads();

    // s_i = sum_j relu(flat[i*32+j]) * w_j ; alpha = sigmoid(s)
    {
        float s = 0.f;
        int base = tid * FN_;
#pragma unroll
        for (int j = 0; j < FN_; j++)
            s = fmaf(fmaxf(convs[base + j], 0.f), wv[j], s);
        alpha[tid] = sigf(s);
    }
    __syncthreads();

    // v_j = sum_i alpha_i * relu(flat[i*32+j])
    if (tid < FN_) {
        float s = 0.f;
        for (int i = 0; i < H_; i++)
            s = fmaf(alpha[i], fmaxf(convs[i * FN_ + tid], 0.f), s);
        vv[tid] = s;
    }
    __syncthreads();

    // new_ht = [htt, v] @ lin2_W.T + lin2_b
    {
        float s = lin2_b[tid];
        const float* w2 = lin2_W + tid * (H_ + FN_);
        for (int kk = 0; kk < H_; kk++) s = fmaf(htt[kk], w2[kk], s);
#pragma unroll
        for (int j = 0; j < FN_; j++) s = fmaf(vv[j], w2[H_ + j], s);
        nh[tid] = s;
    }
    __syncthreads();

    // out = new_ht @ out_W.T + out_b
    if (tid < HOR_) {
        float s = out_b[tid];
        for (int h = 0; h < H_; h++) s = fmaf(nh[h], out_W[tid * H_ + h], s);
        out[(size_t)b * HOR_ + tid] = s;
    }
}

// ---------------- launcher ----------------
extern "C" void kernel_launch(void* const* d_in, const int* in_sizes, int n_in,
                              void* d_out, int out_size) {
    const float* x      = (const float*)d_in[0];
    const float* hW     = (const float*)d_in[1];
    const float* hb     = (const float*)d_in[2];
    const float* W_ih   = (const float*)d_in[3];
    const float* W_hh   = (const float*)d_in[4];
    const float* b_ih   = (const float*)d_in[5];
    const float* b_hh   = (const float*)d_in[6];
    const float* conv_W = (const float*)d_in[7];
    const float* conv_b = (const float*)d_in[8];
    const float* lin1_W = (const float*)d_in[9];
    const float* lin1_b = (const float*)d_in[10];
    const float* lin2_W = (const float*)d_in[11];
    const float* lin2_b = (const float*)d_in[12];
    const float* out_W  = (const float*)d_in[13];
    const float* out_b  = (const float*)d_in[14];
    float* out = (float*)d_out;

    (void)in_sizes; (void)n_in; (void)out_size;

    cudaFuncSetAttribute(lstm_kernel, cudaFuncAttributeMaxDynamicSharedMemorySize,
                         LSTM_SMEM_FLOATS * (int)sizeof(float));

    pack_kernel<<<1024, 256>>>(W_ih, W_hh, b_ih, b_hh);
    lstm_kernel<<<B_ / BM_, 256, LSTM_SMEM_FLOATS * sizeof(float)>>>(x, hW, hb);
    attn_kernel<<<B_, 128>>>(conv_W, conv_b, lin1_W, lin1_b,
                             lin2_W, lin2_b, out_W, out_b, out);
}

// round 2
// speedup vs baseline: 1.0260x; 1.0260x over previous
#include <cuda_runtime.h>

// ---------------- problem constants ----------------
#define B_   2048
#define T_   168
#define H_   128
#define G_   512     // 4*H
#define K2_  256     // concat input dim (128 input + 128 hidden)
#define BM_  16      // batch rows per CTA
#define FN_  32
#define HOR_ 24

// ---------------- device scratch (no allocs allowed) ----------------
__device__ float g_wpack[2 * K2_ * G_];          // [l][k][g]  k-major packed weights (1 MB)
__device__ float g_bsum [2 * G_];                // b_ih + b_hh
__device__ float g_hs   [(size_t)B_ * T_ * H_];  // last-layer hidden at every step (176 MB)

// ---------------- packed f32x2 helpers (sm_100a) ----------------
__device__ __forceinline__ unsigned long long pk2(float x) {
    unsigned long long r;
    asm("mov.b64 %0, {%1, %1};" : "=l"(r) : "f"(x));
    return r;
}
__device__ __forceinline__ void fma2(unsigned long long& d,
                                     unsigned long long a, unsigned long long b) {
    asm("fma.rn.f32x2 %0, %1, %2, %0;" : "+l"(d) : "l"(a), "l"(b));
}
__device__ __forceinline__ float2 unpk(unsigned long long v) {
    float2 f;
    asm("mov.b64 {%0, %1}, %2;" : "=f"(f.x), "=f"(f.y) : "l"(v));
    return f;
}

// ---------------- fast activations (MUFU.TANH) ----------------
__device__ __forceinline__ float tanh_mufu(float x) {
    float r; asm("tanh.approx.f32 %0, %1;" : "=f"(r) : "f"(x)); return r;
}
__device__ __forceinline__ float sigf(float x) {
    return 0.5f * tanh_mufu(0.5f * x) + 0.5f;
}

// ---------------- weight packing: Wpack[l][k][g] ----------------
__global__ void pack_kernel(const float* __restrict__ W_ih, const float* __restrict__ W_hh,
                            const float* __restrict__ b_ih, const float* __restrict__ b_hh) {
    int idx = blockIdx.x * blockDim.x + threadIdx.x;     // 0 .. 262143
    int l = idx >> 17;
    int k = (idx >> 9) & 255;
    int g = idx & 511;
    float v = (k < 128) ? W_ih[l * 65536 + g * 128 + k]
                        : W_hh[l * 65536 + g * 128 + (k - 128)];
    g_wpack[idx] = v;
    if (idx < 2 * G_) g_bsum[idx] = b_ih[idx] + b_hh[idx];
}

// ---------------- per-CTA GEMM: G[16][512] = At^T[16][256] * Wpack + bsum ----------
// At: [256 k][20] transposed activations (rows 0..15 valid, 4-float pad).
// thread: cg = tid&127 -> 4 gate cols [4cg..4cg+3]; rg = tid>>7 -> rows [8rg..8rg+7]
// Accumulators are f32x2 row-pairs: acc[p][c] = rows (r0+2p, r0+2p+1), col 4cg+c.
__device__ __forceinline__ void gemm16(const float* __restrict__ At,    // [256][20]
                                       const float* __restrict__ W,     // [256][512]
                                       const float* __restrict__ bsum,  // [512]
                                       float* __restrict__ Gs,          // [16][512]
                                       int cg, int r0) {
    const float4* W4 = (const float4*)W;     // [256][128]
    float4 bs = ((const float4*)bsum)[cg];
    unsigned long long acc[4][4];
    {
        unsigned long long bb0 = pk2(bs.x), bb1 = pk2(bs.y),
                           bb2 = pk2(bs.z), bb3 = pk2(bs.w);
#pragma unroll
        for (int p = 0; p < 4; p++) {
            acc[p][0] = bb0; acc[p][1] = bb1; acc[p][2] = bb2; acc[p][3] = bb3;
        }
    }

    float4 wn0 = W4[0 * 128 + cg];
    float4 wn1 = W4[1 * 128 + cg];
    float4 wn2 = W4[2 * 128 + cg];
    float4 wn3 = W4[3 * 128 + cg];

    for (int k4 = 0; k4 < 64; k4++) {
        float4 wc0 = wn0, wc1 = wn1, wc2 = wn2, wc3 = wn3;
        int kn = (k4 < 63) ? (k4 + 1) * 4 : 252;   // redundant reload on last iter
        wn0 = W4[(kn + 0) * 128 + cg];
        wn1 = W4[(kn + 1) * 128 + cg];
        wn2 = W4[(kn + 2) * 128 + cg];
        wn3 = W4[(kn + 3) * 128 + cg];
#pragma unroll
        for (int j = 0; j < 4; j++) {
            int k = k4 * 4 + j;
            // rows r0..r0+3 and r0+4..r0+7 at this k (warp-broadcast LDS)
            ulonglong2 aA = *(const ulonglong2*)(At + k * 20 + r0);
            ulonglong2 aB = *(const ulonglong2*)(At + k * 20 + r0 + 4);
            float4 w = (j == 0) ? wc0 : (j == 1) ? wc1 : (j == 2) ? wc2 : wc3;
            unsigned long long wd0 = pk2(w.x), wd1 = pk2(w.y),
                               wd2 = pk2(w.z), wd3 = pk2(w.w);
            fma2(acc[0][0], aA.x, wd0); fma2(acc[0][1], aA.x, wd1);
            fma2(acc[0][2], aA.x, wd2); fma2(acc[0][3], aA.x, wd3);
            fma2(acc[1][0], aA.y, wd0); fma2(acc[1][1], aA.y, wd1);
            fma2(acc[1][2], aA.y, wd2); fma2(acc[1][3], aA.y, wd3);
            fma2(acc[2][0], aB.x, wd0); fma2(acc[2][1], aB.x, wd1);
            fma2(acc[2][2], aB.x, wd2); fma2(acc[2][3], aB.x, wd3);
            fma2(acc[3][0], aB.y, wd0); fma2(acc[3][1], aB.y, wd1);
            fma2(acc[3][2], aB.y, wd2); fma2(acc[3][3], aB.y, wd3);
        }
    }
#pragma unroll
    for (int p = 0; p < 4; p++) {
#pragma unroll
        for (int c = 0; c < 4; c++) {
            float2 v = unpk(acc[p][c]);
            Gs[(r0 + 2 * p) * 512 + 4 * cg + c]       = v.x;
            Gs[(r0 + 2 * p + 1) * 512 + 4 * cg + c]   = v.y;
        }
    }
}

// ---------------- persistent recurrent kernel: 128 CTAs x 16 rows ----------------
// dyn smem layout (floats):
//  At[256][20]  (xc | h0) transposed    5120
//  Bt[256][20]  (h0new | h1) transposed 5120
//  C0[16][128]                          2048
//  C1[16][128]                          2048
//  Gs[16][512]                          8192
//  Xs[16][168]                          2688
#define LSTM_SMEM_FLOATS (5120 + 5120 + 2048 + 2048 + 8192 + 2688)

__global__ __launch_bounds__(256, 1) void lstm_kernel(const float* __restrict__ x,
                                                      const float* __restrict__ hw,
                                                      const float* __restrict__ hb) {
    extern __shared__ float sm[];
    float* At = sm;             // [256][20]
    float* Bt = sm + 5120;      // [256][20]
    float* C0 = sm + 10240;
    float* C1 = sm + 12288;
    float* Gs = sm + 14336;
    float* Xs = sm + 22528;

    int tid = threadIdx.x;
    int b0  = blockIdx.x * BM_;
    int cg  = tid & 127;
    int rg  = tid >> 7;
    int r0  = rg * 8;

    // init hidden/cell state + stage x tile
    for (int i = tid; i < 128 * 16; i += 256) {
        int j = i >> 4, r = i & 15;
        At[(128 + j) * 20 + r] = 0.f;
        Bt[(128 + j) * 20 + r] = 0.f;
    }
    for (int i = tid; i < BM_ * H_; i += 256) { C0[i] = 0.f; C1[i] = 0.f; }
    for (int i = tid; i < BM_ * T_; i += 256) {
        int r = i / T_, t = i - r * T_;
        Xs[r * T_ + t] = x[(size_t)(b0 + r) * T_ + t];
    }
    float hwv = hw[cg];
    float hbv = hb[cg];
    __syncthreads();

    for (int t = 0; t < T_; t++) {
        // xc = relu(x*hw + hb) into At k-rows [0,128)
#pragma unroll
        for (int i = 0; i < 8; i++) {
            int r = rg + 2 * i;
            At[cg * 20 + r] = fmaxf(Xs[r * T_ + t] * hwv + hbv, 0.f);
        }
        __syncthreads();

        // layer 0 gates
        gemm16(At, g_wpack, g_bsum, Gs, cg, r0);
        __syncthreads();

        // cell 0
#pragma unroll
        for (int i = 0; i < 8; i++) {
            int r = rg + 2 * i;
            float ig = Gs[r * 512 + cg];
            float fg = Gs[r * 512 + 128 + cg];
            float gg = Gs[r * 512 + 256 + cg];
            float og = Gs[r * 512 + 384 + cg];
            float c  = sigf(fg) * C0[r * 128 + cg] + sigf(ig) * tanh_mufu(gg);
            float h  = sigf(og) * tanh_mufu(c);
            C0[r * 128 + cg]        = c;
            Bt[cg * 20 + r]         = h;   // layer-1 input (k-rows [0,128))
            At[(128 + cg) * 20 + r] = h;   // next-step layer-0 recurrent input
        }
        __syncthreads();

        // layer 1 gates
        gemm16(Bt, g_wpack + 131072, g_bsum + 512, Gs, cg, r0);
        __syncthreads();

        // cell 1 (+ store hidden history)
#pragma unroll
        for (int i = 0; i < 8; i++) {
            int r = rg + 2 * i;
            float ig = Gs[r * 512 + cg];
            float fg = Gs[r * 512 + 128 + cg];
            float gg = Gs[r * 512 + 256 + cg];
            float og = Gs[r * 512 + 384 + cg];
            float c  = sigf(fg) * C1[r * 128 + cg] + sigf(ig) * tanh_mufu(gg);
            float h  = sigf(og) * tanh_mufu(c);
            C1[r * 128 + cg]        = c;
            Bt[(128 + cg) * 20 + r] = h;
            g_hs[((size_t)(b0 + r) * T_ + t) * H_ + cg] = h;
        }
        // no trailing sync: next write (xc -> At k-rows [0,128)) is disjoint from
        // everything read after it until the post-xc sync, which orders cell1.
    }
}

// ---------------- attention + head: one CTA per batch element ----------------
__global__ __launch_bounds__(128) void attn_kernel(
    const float* __restrict__ conv_W, const float* __restrict__ conv_b,
    const float* __restrict__ lin1_W, const float* __restrict__ lin1_b,
    const float* __restrict__ lin2_W, const float* __restrict__ lin2_b,
    const float* __restrict__ out_W,  const float* __restrict__ out_b,
    float* __restrict__ out) {
    __shared__ float cw[FN_ * T_];     // [32][168], t=167 zero-padded
    __shared__ float convs[FN_ * H_];  // conv[b] flat f*128+k (pre-relu)
    __shared__ float htt[H_];
    __shared__ float wv[FN_];
    __shared__ float alpha[H_];
    __shared__ float vv[FN_];
    __shared__ float nh[H_];

    int tid = threadIdx.x;
    int b   = blockIdx.x;

    for (int i = tid; i < FN_ * T_; i += 128) {
        int f = i / T_, t = i - f * T_;
        cw[i] = (t < T_ - 1) ? conv_W[f * (T_ - 1) + t] : 0.f;
    }
    __syncthreads();

    // conv[b,f,k] = sum_t relu(hs[b,t,k]) * conv_W[f,t]   (thread owns k = tid)
    int k = tid;
    float acc[FN_];
#pragma unroll
    for (int f = 0; f < FN_; f++) acc[f] = 0.f;
    const float* hsb = g_hs + (size_t)b * T_ * H_;
    const float4* cw4 = (const float4*)cw;   // [32][42]
    for (int t4 = 0; t4 < 42; t4++) {
        float h0v = fmaxf(hsb[(t4 * 4 + 0) * H_ + k], 0.f);
        float h1v = fmaxf(hsb[(t4 * 4 + 1) * H_ + k], 0.f);
        float h2v = fmaxf(hsb[(t4 * 4 + 2) * H_ + k], 0.f);
        float h3v = fmaxf(hsb[(t4 * 4 + 3) * H_ + k], 0.f);
#pragma unroll
        for (int f = 0; f < FN_; f++) {
            float4 c4 = cw4[f * 42 + t4];
            acc[f] = fmaf(h0v, c4.x, acc[f]);
            acc[f] = fmaf(h1v, c4.y, acc[f]);
            acc[f] = fmaf(h2v, c4.z, acc[f]);
            acc[f] = fmaf(h3v, c4.w, acc[f]);
        }
    }
#pragma unroll
    for (int f = 0; f < FN_; f++) convs[f * H_ + k] = acc[f] + conv_b[f];
    htt[k] = hsb[(T_ - 1) * H_ + k];
    __syncthreads();

    // w = htt @ lin1_W.T + lin1_b
    if (tid < FN_) {
        float s = lin1_b[tid];
        for (int kk = 0; kk < H_; kk++) s = fmaf(htt[kk], lin1_W[tid * H_ + kk], s);
        wv[tid] = s;
    }
    __syncthreads();

    // s_i = sum_j relu(flat[i*32+j]) * w_j ; alpha = sigmoid(s)
    {
        float s = 0.f;
        int base = tid * FN_;
#pragma unroll
        for (int j = 0; j < FN_; j++)
            s = fmaf(fmaxf(convs[base + j], 0.f), wv[j], s);
        alpha[tid] = sigf(s);
    }
    __syncthreads();

    // v_j = sum_i alpha_i * relu(flat[i*32+j])
    if (tid < FN_) {
        float s = 0.f;
        for (int i = 0; i < H_; i++)
            s = fmaf(alpha[i], fmaxf(convs[i * FN_ + tid], 0.f), s);
        vv[tid] = s;
    }
    __syncthreads();

    // new_ht = [htt, v] @ lin2_W.T + lin2_b
    {
        float s = lin2_b[tid];
        const float* w2 = lin2_W + tid * (H_ + FN_);
        for (int kk = 0; kk < H_; kk++) s = fmaf(htt[kk], w2[kk], s);
#pragma unroll
        for (int j = 0; j < FN_; j++) s = fmaf(vv[j], w2[H_ + j], s);
        nh[tid] = s;
    }
    __syncthreads();

    // out = new_ht @ out_W.T + out_b
    if (tid < HOR_) {
        float s = out_b[tid];
        for (int h = 0; h < H_; h++) s = fmaf(nh[h], out_W[tid * H_ + h], s);
        out[(size_t)b * HOR_ + tid] = s;
    }
}

// ---------------- launcher ----------------
extern "C" void kernel_launch(void* const* d_in, const int* in_sizes, int n_in,
                              void* d_out, int out_size) {
    const float* x      = (const float*)d_in[0];
    const float* hW     = (const float*)d_in[1];
    const float* hb     = (const float*)d_in[2];
    const float* W_ih   = (const float*)d_in[3];
    const float* W_hh   = (const float*)d_in[4];
    const float* b_ih   = (const float*)d_in[5];
    const float* b_hh   = (const float*)d_in[6];
    const float* conv_W = (const float*)d_in[7];
    const float* conv_b = (const float*)d_in[8];
    const float* lin1_W = (const float*)d_in[9];
    const float* lin1_b = (const float*)d_in[10];
    const float* lin2_W = (const float*)d_in[11];
    const float* lin2_b = (const float*)d_in[12];
    const float* out_W  = (const float*)d_in[13];
    const float* out_b  = (const float*)d_in[14];
    float* out = (float*)d_out;

    (void)in_sizes; (void)n_in; (void)out_size;

    cudaFuncSetAttribute(lstm_kernel, cudaFuncAttributeMaxDynamicSharedMemorySize,
                         LSTM_SMEM_FLOATS * (int)sizeof(float));

    pack_kernel<<<1024, 256>>>(W_ih, W_hh, b_ih, b_hh);
    lstm_kernel<<<B_ / BM_, 256, LSTM_SMEM_FLOATS * sizeof(float)>>>(x, hW, hb);
    attn_kernel<<<B_, 128>>>(conv_W, conv_b, lin1_W, lin1_b,
                             lin2_W, lin2_b, out_W, out_b, out);
}

// round 3
// speedup vs baseline: 1.0263x; 1.0002x over previous
#include <cuda_runtime.h>

// ---------------- problem constants ----------------
#define B_   2048
#define T_   168
#define H_   128
#define G_   512     // 4*H
#define K2_  256     // concat input dim (128 input + 128 hidden)
#define BM_  16      // batch rows per CTA
#define FN_  32
#define HOR_ 24

// ---------------- device scratch (no allocs allowed) ----------------
__device__ float g_wpack[2 * K2_ * G_];          // [l][k][g]  k-major packed weights (1 MB)
__device__ float g_bsum [2 * G_];                // b_ih + b_hh
__device__ float g_hs   [(size_t)B_ * T_ * H_];  // last-layer hidden at every step (176 MB)

// ---------------- packed f32x2 helpers (sm_100a) ----------------
__device__ __forceinline__ unsigned long long pk2(float x) {
    unsigned long long r;
    asm("mov.b64 %0, {%1, %1};" : "=l"(r) : "f"(x));
    return r;
}
__device__ __forceinline__ void fma2(unsigned long long& d,
                                     unsigned long long a, unsigned long long b) {
    asm("fma.rn.f32x2 %0, %1, %2, %0;" : "+l"(d) : "l"(a), "l"(b));
}
__device__ __forceinline__ float2 unpk(unsigned long long v) {
    float2 f;
    asm("mov.b64 {%0, %1}, %2;" : "=f"(f.x), "=f"(f.y) : "l"(v));
    return f;
}

// ---------------- fast activations (MUFU.TANH) ----------------
__device__ __forceinline__ float tanh_mufu(float x) {
    float r; asm("tanh.approx.f32 %0, %1;" : "=f"(r) : "f"(x)); return r;
}
__device__ __forceinline__ float sigf(float x) {
    return 0.5f * tanh_mufu(0.5f * x) + 0.5f;
}

// ---------------- weight packing: Wpack[l][k][g] ----------------
__global__ void pack_kernel(const float* __restrict__ W_ih, const float* __restrict__ W_hh,
                            const float* __restrict__ b_ih, const float* __restrict__ b_hh) {
    int idx = blockIdx.x * blockDim.x + threadIdx.x;     // 0 .. 262143
    int l = idx >> 17;
    int k = (idx >> 9) & 255;
    int g = idx & 511;
    float v = (k < 128) ? W_ih[l * 65536 + g * 128 + k]
                        : W_hh[l * 65536 + g * 128 + (k - 128)];
    g_wpack[idx] = v;
    if (idx < 2 * G_) g_bsum[idx] = b_ih[idx] + b_hh[idx];
}

// ---------------- per-CTA GEMM: G[16][512] = At^T[16][256] * Wpack + bsum ----------
// At: [256 k][20] transposed activations (rows 0..15 valid, 4-float pad).
// thread: cg = tid&127 -> 4 gate cols [4cg..4cg+3]; rg = tid>>7 -> rows [8rg..8rg+7]
// Accumulators are f32x2 row-pairs: acc[p][c] = rows (r0+2p, r0+2p+1), col 4cg+c.
__device__ __forceinline__ void gemm16(const float* __restrict__ At,    // [256][20]
                                       const float* __restrict__ W,     // [256][512]
                                       const float* __restrict__ bsum,  // [512]
                                       float* __restrict__ Gs,          // [16][512]
                                       int cg, int r0) {
    const float4* W4 = (const float4*)W;     // [256][128]
    float4 bs = ((const float4*)bsum)[cg];
    unsigned long long acc[4][4];
    {
        unsigned long long bb0 = pk2(bs.x), bb1 = pk2(bs.y),
                           bb2 = pk2(bs.z), bb3 = pk2(bs.w);
#pragma unroll
        for (int p = 0; p < 4; p++) {
            acc[p][0] = bb0; acc[p][1] = bb1; acc[p][2] = bb2; acc[p][3] = bb3;
        }
    }

    float4 wn0 = W4[0 * 128 + cg];
    float4 wn1 = W4[1 * 128 + cg];
    float4 wn2 = W4[2 * 128 + cg];
    float4 wn3 = W4[3 * 128 + cg];

    for (int k4 = 0; k4 < 64; k4++) {
        float4 wc0 = wn0, wc1 = wn1, wc2 = wn2, wc3 = wn3;
        int kn = (k4 < 63) ? (k4 + 1) * 4 : 252;   // redundant reload on last iter
        wn0 = W4[(kn + 0) * 128 + cg];
        wn1 = W4[(kn + 1) * 128 + cg];
        wn2 = W4[(kn + 2) * 128 + cg];
        wn3 = W4[(kn + 3) * 128 + cg];
#pragma unroll
        for (int j = 0; j < 4; j++) {
            int k = k4 * 4 + j;
            // rows r0..r0+3 and r0+4..r0+7 at this k (warp-broadcast LDS)
            ulonglong2 aA = *(const ulonglong2*)(At + k * 20 + r0);
            ulonglong2 aB = *(const ulonglong2*)(At + k * 20 + r0 + 4);
            float4 w = (j == 0) ? wc0 : (j == 1) ? wc1 : (j == 2) ? wc2 : wc3;
            unsigned long long wd0 = pk2(w.x), wd1 = pk2(w.y),
                               wd2 = pk2(w.z), wd3 = pk2(w.w);
            fma2(acc[0][0], aA.x, wd0); fma2(acc[0][1], aA.x, wd1);
            fma2(acc[0][2], aA.x, wd2); fma2(acc[0][3], aA.x, wd3);
            fma2(acc[1][0], aA.y, wd0); fma2(acc[1][1], aA.y, wd1);
            fma2(acc[1][2], aA.y, wd2); fma2(acc[1][3], aA.y, wd3);
            fma2(acc[2][0], aB.x, wd0); fma2(acc[2][1], aB.x, wd1);
            fma2(acc[2][2], aB.x, wd2); fma2(acc[2][3], aB.x, wd3);
            fma2(acc[3][0], aB.y, wd0); fma2(acc[3][1], aB.y, wd1);
            fma2(acc[3][2], aB.y, wd2); fma2(acc[3][3], aB.y, wd3);
        }
    }
#pragma unroll
    for (int p = 0; p < 4; p++) {
#pragma unroll
        for (int c = 0; c < 4; c++) {
            float2 v = unpk(acc[p][c]);
            Gs[(r0 + 2 * p) * 512 + 4 * cg + c]       = v.x;
            Gs[(r0 + 2 * p + 1) * 512 + 4 * cg + c]   = v.y;
        }
    }
}

// ---------------- persistent recurrent kernel: 128 CTAs x 16 rows ----------------
// dyn smem layout (floats):
//  At[256][20]  (xc | h0) transposed    5120
//  Bt[256][20]  (h0new | h1) transposed 5120
//  C0[16][128]                          2048
//  C1[16][128]                          2048
//  Gs[16][512]                          8192
//  Xs[16][168]                          2688
#define LSTM_SMEM_FLOATS (5120 + 5120 + 2048 + 2048 + 8192 + 2688)

__global__ __launch_bounds__(256, 1) void lstm_kernel(const float* __restrict__ x,
                                                      const float* __restrict__ hw,
                                                      const float* __restrict__ hb) {
    extern __shared__ float sm[];
    float* At = sm;             // [256][20]
    float* Bt = sm + 5120;      // [256][20]
    float* C0 = sm + 10240;
    float* C1 = sm + 12288;
    float* Gs = sm + 14336;
    float* Xs = sm + 22528;

    int tid = threadIdx.x;
    int b0  = blockIdx.x * BM_;
    int cg  = tid & 127;
    int rg  = tid >> 7;
    int r0  = rg * 8;

    // init hidden/cell state + stage x tile
    for (int i = tid; i < 128 * 16; i += 256) {
        int j = i >> 4, r = i & 15;
        At[(128 + j) * 20 + r] = 0.f;
        Bt[(128 + j) * 20 + r] = 0.f;
    }
    for (int i = tid; i < BM_ * H_; i += 256) { C0[i] = 0.f; C1[i] = 0.f; }
    for (int i = tid; i < BM_ * T_; i += 256) {
        int r = i / T_, t = i - r * T_;
        Xs[r * T_ + t] = x[(size_t)(b0 + r) * T_ + t];
    }
    float hwv = hw[cg];
    float hbv = hb[cg];
    __syncthreads();

    for (int t = 0; t < T_; t++) {
        // xc = relu(x*hw + hb) into At k-rows [0,128)
#pragma unroll
        for (int i = 0; i < 8; i++) {
            int r = rg + 2 * i;
            At[cg * 20 + r] = fmaxf(Xs[r * T_ + t] * hwv + hbv, 0.f);
        }
        __syncthreads();

        // layer 0 gates
        gemm16(At, g_wpack, g_bsum, Gs, cg, r0);
        __syncthreads();

        // cell 0
#pragma unroll
        for (int i = 0; i < 8; i++) {
            int r = rg + 2 * i;
            float ig = Gs[r * 512 + cg];
            float fg = Gs[r * 512 + 128 + cg];
            float gg = Gs[r * 512 + 256 + cg];
            float og = Gs[r * 512 + 384 + cg];
            float c  = sigf(fg) * C0[r * 128 + cg] + sigf(ig) * tanh_mufu(gg);
            float h  = sigf(og) * tanh_mufu(c);
            C0[r * 128 + cg]        = c;
            Bt[cg * 20 + r]         = h;   // layer-1 input (k-rows [0,128))
            At[(128 + cg) * 20 + r] = h;   // next-step layer-0 recurrent input
        }
        __syncthreads();

        // layer 1 gates
        gemm16(Bt, g_wpack + 131072, g_bsum + 512, Gs, cg, r0);
        __syncthreads();

        // cell 1 (+ store hidden history)
#pragma unroll
        for (int i = 0; i < 8; i++) {
            int r = rg + 2 * i;
            float ig = Gs[r * 512 + cg];
            float fg = Gs[r * 512 + 128 + cg];
            float gg = Gs[r * 512 + 256 + cg];
            float og = Gs[r * 512 + 384 + cg];
            float c  = sigf(fg) * C1[r * 128 + cg] + sigf(ig) * tanh_mufu(gg);
            float h  = sigf(og) * tanh_mufu(c);
            C1[r * 128 + cg]        = c;
            Bt[(128 + cg) * 20 + r] = h;
            g_hs[((size_t)(b0 + r) * T_ + t) * H_ + cg] = h;
        }
        // no trailing sync: next write (xc -> At k-rows [0,128)) is disjoint from
        // everything read after it until the post-xc sync, which orders cell1.
    }
}

// ---------------- attention + head: one CTA per batch element ----------------
__global__ __launch_bounds__(128) void attn_kernel(
    const float* __restrict__ conv_W, const float* __restrict__ conv_b,
    const float* __restrict__ lin1_W, const float* __restrict__ lin1_b,
    const float* __restrict__ lin2_W, const float* __restrict__ lin2_b,
    const float* __restrict__ out_W,  const float* __restrict__ out_b,
    float* __restrict__ out) {
    __shared__ float cw[FN_ * T_];     // [32][168], t=167 zero-padded
    __shared__ float convs[FN_ * H_];  // conv[b] flat f*128+k (pre-relu)
    __shared__ float htt[H_];
    __shared__ float wv[FN_];
    __shared__ float alpha[H_];
    __shared__ float vv[FN_];
    __shared__ float nh[H_];

    int tid = threadIdx.x;
    int b   = blockIdx.x;

    for (int i = tid; i < FN_ * T_; i += 128) {
        int f = i / T_, t = i - f * T_;
        cw[i] = (t < T_ - 1) ? conv_W[f * (T_ - 1) + t] : 0.f;
    }
    __syncthreads();

    // conv[b,f,k] = sum_t relu(hs[b,t,k]) * conv_W[f,t]   (thread owns k = tid)
    int k = tid;
    float acc[FN_];
#pragma unroll
    for (int f = 0; f < FN_; f++) acc[f] = 0.f;
    const float* hsb = g_hs + (size_t)b * T_ * H_;
    const float4* cw4 = (const float4*)cw;   // [32][42]
    for (int t4 = 0; t4 < 42; t4++) {
        float h0v = fmaxf(hsb[(t4 * 4 + 0) * H_ + k], 0.f);
        float h1v = fmaxf(hsb[(t4 * 4 + 1) * H_ + k], 0.f);
        float h2v = fmaxf(hsb[(t4 * 4 + 2) * H_ + k], 0.f);
        float h3v = fmaxf(hsb[(t4 * 4 + 3) * H_ + k], 0.f);
#pragma unroll
        for (int f = 0; f < FN_; f++) {
            float4 c4 = cw4[f * 42 + t4];
            acc[f] = fmaf(h0v, c4.x, acc[f]);
            acc[f] = fmaf(h1v, c4.y, acc[f]);
            acc[f] = fmaf(h2v, c4.z, acc[f]);
            acc[f] = fmaf(h3v, c4.w, acc[f]);
        }
    }
#pragma unroll
    for (int f = 0; f < FN_; f++) convs[f * H_ + k] = acc[f] + conv_b[f];
    htt[k] = hsb[(T_ - 1) * H_ + k];
    __syncthreads();

    // w = htt @ lin1_W.T + lin1_b
    if (tid < FN_) {
        float s = lin1_b[tid];
        for (int kk = 0; kk < H_; kk++) s = fmaf(htt[kk], lin1_W[tid * H_ + kk], s);
        wv[tid] = s;
    }
    __syncthreads();

    // s_i = sum_j relu(flat[i*32+j]) * w_j ; alpha = sigmoid(s)
    {
        float s = 0.f;
        int base = tid * FN_;
#pragma unroll
        for (int j = 0; j < FN_; j++)
            s = fmaf(fmaxf(convs[base + j], 0.f), wv[j], s);
        alpha[tid] = sigf(s);
    }
    __syncthreads();

    // v_j = sum_i alpha_i * relu(flat[i*32+j])
    if (tid < FN_) {
        float s = 0.f;
        for (int i = 0; i < H_; i++)
            s = fmaf(alpha[i], fmaxf(convs[i * FN_ + tid], 0.f), s);
        vv[tid] = s;
    }
    __syncthreads();

    // new_ht = [htt, v] @ lin2_W.T + lin2_b
    {
        float s = lin2_b[tid];
        const float* w2 = lin2_W + tid * (H_ + FN_);
        for (int kk = 0; kk < H_; kk++) s = fmaf(htt[kk], w2[kk], s);
#pragma unroll
        for (int j = 0; j < FN_; j++) s = fmaf(vv[j], w2[H_ + j], s);
        nh[tid] = s;
    }
    __syncthreads();

    // out = new_ht @ out_W.T + out_b
    if (tid < HOR_) {
        float s = out_b[tid];
        for (int h = 0; h < H_; h++) s = fmaf(nh[h], out_W[tid * H_ + h], s);
        out[(size_t)b * HOR_ + tid] = s;
    }
}

// ---------------- launcher ----------------
extern "C" void kernel_launch(void* const* d_in, const int* in_sizes, int n_in,
                              void* d_out, int out_size) {
    const float* x      = (const float*)d_in[0];
    const float* hW     = (const float*)d_in[1];
    const float* hb     = (const float*)d_in[2];
    const float* W_ih   = (const float*)d_in[3];
    const float* W_hh   = (const float*)d_in[4];
    const float* b_ih   = (const float*)d_in[5];
    const float* b_hh   = (const float*)d_in[6];
    const float* conv_W = (const float*)d_in[7];
    const float* conv_b = (const float*)d_in[8];
    const float* lin1_W = (const float*)d_in[9];
    const float* lin1_b = (const float*)d_in[10];
    const float* lin2_W = (const float*)d_in[11];
    const float* lin2_b = (const float*)d_in[12];
    const float* out_W  = (const float*)d_in[13];
    const float* out_b  = (const float*)d_in[14];
    float* out = (float*)d_out;

    (void)in_sizes; (void)n_in; (void)out_size;

    cudaFuncSetAttribute(lstm_kernel, cudaFuncAttributeMaxDynamicSharedMemorySize,
                         LSTM_SMEM_FLOATS * (int)sizeof(float));

    pack_kernel<<<1024, 256>>>(W_ih, W_hh, b_ih, b_hh);
    lstm_kernel<<<B_ / BM_, 256, LSTM_SMEM_FLOATS * sizeof(float)>>>(x, hW, hb);
    attn_kernel<<<B_, 128>>>(conv_W, conv_b, lin1_W, lin1_b,
                             lin2_W, lin2_b, out_W, out_b, out);
}